// round 5
// baseline (speedup 1.0000x reference)
#include <cuda_runtime.h>
#include <math.h>

#define NN 8192
#define FD 128
#define HEPS 1e-7f
#define MAXT (1.0f - 1e-6f)
#define CAP 384   // per-row nnz capacity (mean 82, sd 9 -> 33 sigma headroom)

// Scratch (no allocations allowed)
__device__ float g_V[NN * FD];       // log0(h_add(exp0(log0(x)@embed), embed_bias))
__device__ float g_W[NN * 2 * FD];   // log0(concat(x, exp0(adj@V)))

__device__ __forceinline__ float wsum(float v) {
#pragma unroll
    for (int o = 16; o > 0; o >>= 1) v += __shfl_xor_sync(0xffffffffu, v, o);
    return v;
}

// Mobius epilogue for 2 rows/warp. Warp owns full rows (lane -> 4 cols).
// MODE 0: log0(h_add(exp0(T),b)); MODE 1: h_add(exp0(T),b)
template <int MODE>
__device__ __forceinline__ void mobius_epi2(float acc[2][4], const float* __restrict__ bias,
                                            int br, int wid, int lane,
                                            float* __restrict__ out) {
    float4 bv = ((const float4*)bias)[lane];
    float y2 = wsum(bv.x * bv.x + bv.y * bv.y + bv.z * bv.z + bv.w * bv.w);
#pragma unroll
    for (int r = 0; r < 2; r++) {
        int row = br + wid * 2 + r;
        float t0 = acc[r][0], t1 = acc[r][1], t2 = acc[r][2], t3 = acc[r][3];
        float ss  = wsum(t0 * t0 + t1 * t1 + t2 * t2 + t3 * t3);
        float dtb = wsum(t0 * bv.x + t1 * bv.y + t2 * bv.z + t3 * bv.w);
        float n = fmaxf(sqrtf(ss), HEPS);
        float s = tanhf(n) / n;                       // exp0 scale
        float x2 = s * s * ss;
        float xy = s * dtb;
        float cnum = 1.f + 2.f * xy + y2;
        float cx = 1.f - x2;
        float inv = 1.f / fmaxf(1.f + 2.f * xy + x2 * y2, HEPS);
        float o0 = (cnum * s * t0 + cx * bv.x) * inv;
        float o1 = (cnum * s * t1 + cx * bv.y) * inv;
        float o2 = (cnum * s * t2 + cx * bv.z) * inv;
        float o3 = (cnum * s * t3 + cx * bv.w) * inv;
        if (MODE == 0) {
            float sso = wsum(o0 * o0 + o1 * o1 + o2 * o2 + o3 * o3);
            float no = fmaxf(sqrtf(sso), HEPS);
            float so = atanhf(fminf(no, MAXT)) / no;
            o0 *= so; o1 *= so; o2 *= so; o3 *= so;
        }
        ((float4*)(out + (size_t)row * FD))[lane] = make_float4(o0, o1, o2, o3);
    }
}

// ---------------------------------------------------------------------------
// GEMM1 fused with log map: V = log0(h_add(exp0(log0(x) @ embed), eb))
// Block 512 thr = 16 warps x 2 rows (BM=32). Full A tile in smem, log0 in-smem.
// ---------------------------------------------------------------------------
__global__ __launch_bounds__(512) void k_gemm1(
    const float* __restrict__ X, const float* __restrict__ B,
    const float* __restrict__ bias, float* __restrict__ out) {
    __shared__ float As[32][FD];
    __shared__ float Bs[32][FD];
    const int tid = threadIdx.x;
    const int lane = tid & 31;
    const int wid = tid >> 5;        // 0..15
    const int br = blockIdx.x * 32;

    // load full 32x128 A tile (1024 float4 / 512 threads = 2 iters)
#pragma unroll
    for (int i = 0; i < 2; i++) {
        int idx4 = tid + i * 512;
        int r = idx4 >> 5, c4 = idx4 & 31;
        ((float4*)As[r])[c4] = ((const float4*)(X + (size_t)(br + r) * FD))[c4];
    }
    __syncthreads();

    // log0 scaling: warp wid owns rows wid*2, wid*2+1
#pragma unroll
    for (int r = 0; r < 2; r++) {
        int row = wid * 2 + r;
        float4 v = ((float4*)As[row])[lane];
        float ss = wsum(v.x * v.x + v.y * v.y + v.z * v.z + v.w * v.w);
        float n = fmaxf(sqrtf(ss), HEPS);
        float s = atanhf(fminf(n, MAXT)) / n;
        ((float4*)As[row])[lane] = make_float4(v.x * s, v.y * s, v.z * s, v.w * s);
    }

    float acc[2][4];
#pragma unroll
    for (int r = 0; r < 2; r++)
#pragma unroll
        for (int c = 0; c < 4; c++) acc[r][c] = 0.f;

    for (int k0 = 0; k0 < FD; k0 += 32) {
        __syncthreads();
#pragma unroll
        for (int i = 0; i < 2; i++) {
            int idx4 = tid + i * 512;
            int k = idx4 >> 5, c4 = idx4 & 31;
            ((float4*)Bs[k])[c4] = ((const float4*)(B + (size_t)(k0 + k) * FD))[c4];
        }
        __syncthreads();
#pragma unroll
        for (int k4 = 0; k4 < 8; k4++) {
            float4 b0 = ((float4*)Bs[k4 * 4 + 0])[lane];
            float4 b1 = ((float4*)Bs[k4 * 4 + 1])[lane];
            float4 b2 = ((float4*)Bs[k4 * 4 + 2])[lane];
            float4 b3 = ((float4*)Bs[k4 * 4 + 3])[lane];
#pragma unroll
            for (int r = 0; r < 2; r++) {
                float4 a = *(const float4*)&As[wid * 2 + r][k0 + k4 * 4];
                acc[r][0] += a.x * b0.x + a.y * b1.x + a.z * b2.x + a.w * b3.x;
                acc[r][1] += a.x * b0.y + a.y * b1.y + a.z * b2.y + a.w * b3.y;
                acc[r][2] += a.x * b0.z + a.y * b1.z + a.z * b2.z + a.w * b3.z;
                acc[r][3] += a.x * b0.w + a.y * b1.w + a.z * b2.w + a.w * b3.w;
            }
        }
    }
    mobius_epi2<0>(acc, bias, br, wid, lane, out);
}

// ---------------------------------------------------------------------------
// GEMM2: out = h_add(exp0(W @ layer), lb), KD = 256. 16 warps x 2 rows.
// ---------------------------------------------------------------------------
__global__ __launch_bounds__(512) void k_gemm2(
    const float* __restrict__ A, const float* __restrict__ B,
    const float* __restrict__ bias, float* __restrict__ out) {
    __shared__ float As[32][32];
    __shared__ float Bs[32][FD];
    const int tid = threadIdx.x;
    const int lane = tid & 31;
    const int wid = tid >> 5;
    const int br = blockIdx.x * 32;

    float acc[2][4];
#pragma unroll
    for (int r = 0; r < 2; r++)
#pragma unroll
        for (int c = 0; c < 4; c++) acc[r][c] = 0.f;

    for (int k0 = 0; k0 < 2 * FD; k0 += 32) {
        __syncthreads();
        if (tid < 256) {   // 32x32 A chunk: 256 float4
            int r = tid >> 3, c4 = tid & 7;
            ((float4*)As[r])[c4] =
                ((const float4*)(A + (size_t)(br + r) * (2 * FD) + k0))[c4];
        }
#pragma unroll
        for (int i = 0; i < 2; i++) {
            int idx4 = tid + i * 512;
            int k = idx4 >> 5, c4 = idx4 & 31;
            ((float4*)Bs[k])[c4] = ((const float4*)(B + (size_t)(k0 + k) * FD))[c4];
        }
        __syncthreads();
#pragma unroll
        for (int k4 = 0; k4 < 8; k4++) {
            float4 b0 = ((float4*)Bs[k4 * 4 + 0])[lane];
            float4 b1 = ((float4*)Bs[k4 * 4 + 1])[lane];
            float4 b2 = ((float4*)Bs[k4 * 4 + 2])[lane];
            float4 b3 = ((float4*)Bs[k4 * 4 + 3])[lane];
#pragma unroll
            for (int r = 0; r < 2; r++) {
                float4 a = ((float4*)As[wid * 2 + r])[k4];
                acc[r][0] += a.x * b0.x + a.y * b1.x + a.z * b2.x + a.w * b3.x;
                acc[r][1] += a.x * b0.y + a.y * b1.y + a.z * b2.y + a.w * b3.y;
                acc[r][2] += a.x * b0.z + a.y * b1.z + a.z * b2.z + a.w * b3.z;
                acc[r][3] += a.x * b0.w + a.y * b1.w + a.z * b2.w + a.w * b3.w;
            }
        }
    }
    mobius_epi2<1>(acc, bias, br, wid, lane, out);
}

// ---------------------------------------------------------------------------
// SpMM + concat/log fusion: W = log0(concat(x, exp0(adj @ V)))
// One warp per row. Phase A: stream adj row, compact (col,val) into smem via
// ballot+popc prefix. Phase B: 8-wide unrolled gather of V rows (high MLP).
// ---------------------------------------------------------------------------
__global__ __launch_bounds__(256) void k_spmm_fused(
    const float* __restrict__ adj, const float* __restrict__ V,
    const float* __restrict__ x, float* __restrict__ W) {
    __shared__ int   s_col[8][CAP];
    __shared__ float s_val[8][CAP];
    const int wrp = threadIdx.x >> 5;
    const int lane = threadIdx.x & 31;
    const int row = (blockIdx.x * blockDim.x + threadIdx.x) >> 5;
    if (row >= NN) return;
    int*   cols = s_col[wrp];
    float* vals = s_val[wrp];
    const float* arow = adj + (size_t)row * NN;
    const unsigned lt = (1u << lane) - 1u;

    // Phase A: compact nonzeros (prefetched double-buffer stream)
    int cnt = 0;
    float cur[4];
#pragma unroll
    for (int q = 0; q < 4; q++) cur[q] = arow[q * 32 + lane];
    for (int base = 0; base < NN; base += 128) {
        float nxt[4] = {0.f, 0.f, 0.f, 0.f};
        int nb = base + 128;
        if (nb < NN) {
#pragma unroll
            for (int q = 0; q < 4; q++) nxt[q] = arow[nb + q * 32 + lane];
        }
#pragma unroll
        for (int q = 0; q < 4; q++) {
            float a = cur[q];
            unsigned m = __ballot_sync(0xffffffffu, a != 0.f);
            if (a != 0.f) {
                int pos = cnt + __popc(m & lt);
                if (pos < CAP) { cols[pos] = base + q * 32 + lane; vals[pos] = a; }
            }
            cnt += __popc(m);
        }
#pragma unroll
        for (int q = 0; q < 4; q++) cur[q] = nxt[q];
    }
    if (cnt > CAP) cnt = CAP;
    __syncwarp();

    // Phase B: 8-wide gather of V rows
    float ax = 0.f, ay = 0.f, az = 0.f, aw = 0.f;
    int i = 0;
    for (; i + 8 <= cnt; i += 8) {
        int   c[8];
        float wv[8];
#pragma unroll
        for (int j = 0; j < 8; j++) { c[j] = cols[i + j]; wv[j] = vals[i + j]; }
#pragma unroll
        for (int j = 0; j < 8; j++) {
            float4 v = ((const float4*)(V + (size_t)c[j] * FD))[lane];
            ax += wv[j] * v.x; ay += wv[j] * v.y; az += wv[j] * v.z; aw += wv[j] * v.w;
        }
    }
    for (; i < cnt; i++) {
        int cc = cols[i]; float wv = vals[i];
        float4 v = ((const float4*)(V + (size_t)cc * FD))[lane];
        ax += wv * v.x; ay += wv * v.y; az += wv * v.z; aw += wv * v.w;
    }

    // fused epilogue: W = log0(concat(x, exp0(AV)))
    float ssa = wsum(ax * ax + ay * ay + az * az + aw * aw);
    float na = fmaxf(sqrtf(ssa), HEPS);
    float sa = tanhf(na) / na;                 // neigh = sa * AV
    float4 xv = ((const float4*)(x + (size_t)row * FD))[lane];
    float ssx = wsum(xv.x * xv.x + xv.y * xv.y + xv.z * xv.z + xv.w * xv.w);
    float tot = ssx + sa * sa * ssa;           // ||concat||^2
    float n = fmaxf(sqrtf(tot), HEPS);
    float s = atanhf(fminf(n, MAXT)) / n;
    float* wr = W + (size_t)row * 2 * FD;
    ((float4*)wr)[lane] = make_float4(s * xv.x, s * xv.y, s * xv.z, s * xv.w);
    float sb = s * sa;
    ((float4*)(wr + FD))[lane] = make_float4(sb * ax, sb * ay, sb * az, sb * aw);
}

// ---------------------------------------------------------------------------
extern "C" void kernel_launch(void* const* d_in, const int* in_sizes, int n_in,
                              void* d_out, int out_size) {
    const float* x     = (const float*)d_in[0];
    const float* adj   = (const float*)d_in[1];
    const float* embed = (const float*)d_in[2];
    const float* layer = (const float*)d_in[3];
    const float* eb    = (const float*)d_in[4];
    const float* lb    = (const float*)d_in[5];
    float* out = (float*)d_out;
    (void)in_sizes; (void)n_in; (void)out_size;

    float *pV, *pW;
    cudaGetSymbolAddress((void**)&pV, g_V);
    cudaGetSymbolAddress((void**)&pW, g_W);

    // 1. V = log0(h_add(exp0(log0(x) @ embed), eb))
    k_gemm1<<<NN / 32, 512>>>(x, embed, eb, pV);
    // 2. W = log0(concat(x, exp0(adj @ V)))
    k_spmm_fused<<<NN / 8, 256>>>(adj, pV, x, pW);
    // 3. out = h_add(exp0(W @ layer), lb)
    k_gemm2<<<NN / 32, 512>>>(pW, layer, lb, out);
}

// round 6
// speedup vs baseline: 1.3984x; 1.3984x over previous
#include <cuda_runtime.h>
#include <math.h>

#define NN 8192
#define FD 128
#define HEPS 1e-7f
#define MAXT (1.0f - 1e-6f)

// Scratch (no allocations allowed)
__device__ float g_V[NN * FD];       // log0(h_add(exp0(log0(x)@embed), embed_bias))
__device__ float g_W[NN * 2 * FD];   // log0(concat(x, exp0(adj@V)))

__device__ __forceinline__ float wsum(float v) {
#pragma unroll
    for (int o = 16; o > 0; o >>= 1) v += __shfl_xor_sync(0xffffffffu, v, o);
    return v;
}

// Mobius epilogue for 4 rows/warp. Warp owns full rows (lane -> 4 cols).
// MODE 0: log0(h_add(exp0(T),b)); MODE 1: h_add(exp0(T),b)
template <int MODE>
__device__ __forceinline__ void mobius_epi4(float acc[4][4], const float* __restrict__ bias,
                                            int br, int wid, int lane,
                                            float* __restrict__ out) {
    float4 bv = ((const float4*)bias)[lane];
    float y2 = wsum(bv.x * bv.x + bv.y * bv.y + bv.z * bv.z + bv.w * bv.w);
#pragma unroll
    for (int r = 0; r < 4; r++) {
        int row = br + wid * 4 + r;
        float t0 = acc[r][0], t1 = acc[r][1], t2 = acc[r][2], t3 = acc[r][3];
        float ss  = wsum(t0 * t0 + t1 * t1 + t2 * t2 + t3 * t3);
        float dtb = wsum(t0 * bv.x + t1 * bv.y + t2 * bv.z + t3 * bv.w);
        float n = fmaxf(sqrtf(ss), HEPS);
        float s = tanhf(n) / n;                       // exp0 scale
        float x2 = s * s * ss;
        float xy = s * dtb;
        float cnum = 1.f + 2.f * xy + y2;
        float cx = 1.f - x2;
        float inv = 1.f / fmaxf(1.f + 2.f * xy + x2 * y2, HEPS);
        float o0 = (cnum * s * t0 + cx * bv.x) * inv;
        float o1 = (cnum * s * t1 + cx * bv.y) * inv;
        float o2 = (cnum * s * t2 + cx * bv.z) * inv;
        float o3 = (cnum * s * t3 + cx * bv.w) * inv;
        if (MODE == 0) {
            float sso = wsum(o0 * o0 + o1 * o1 + o2 * o2 + o3 * o3);
            float no = fmaxf(sqrtf(sso), HEPS);
            float so = atanhf(fminf(no, MAXT)) / no;
            o0 *= so; o1 *= so; o2 *= so; o3 *= so;
        }
        ((float4*)(out + (size_t)row * FD))[lane] = make_float4(o0, o1, o2, o3);
    }
}

// ---------------------------------------------------------------------------
// GEMM1 fused with log map: V = log0(h_add(exp0(log0(x) @ embed), eb))
// Block 256 thr = 8 warps x 4 rows (BM=32). ENTIRE 128x128 B in smem (64KB)
// + full A tile (16KB). ONE barrier; inner loop is pure LDS+FFMA, pipelined.
// ---------------------------------------------------------------------------
__global__ __launch_bounds__(256) void k_gemm1(
    const float* __restrict__ X, const float* __restrict__ B,
    const float* __restrict__ bias, float* __restrict__ out) {
    extern __shared__ float sm[];
    float (*As)[FD] = (float(*)[FD])sm;             // 32 x 128
    float (*Bs)[FD] = (float(*)[FD])(sm + 32 * FD); // 128 x 128
    const int tid = threadIdx.x;
    const int lane = tid & 31;
    const int wid = tid >> 5;        // 0..7
    const int br = blockIdx.x * 32;

    // load A tile: 1024 float4 / 256 thr = 4 iters
#pragma unroll
    for (int i = 0; i < 4; i++) {
        int idx4 = tid + i * 256;
        int r = idx4 >> 5, c4 = idx4 & 31;
        ((float4*)As[r])[c4] = ((const float4*)(X + (size_t)(br + r) * FD))[c4];
    }
    // load full B: 4096 float4 / 256 thr = 16 iters
#pragma unroll
    for (int i = 0; i < 16; i++) {
        int idx4 = tid + i * 256;
        int k = idx4 >> 5, c4 = idx4 & 31;
        ((float4*)Bs[k])[c4] = ((const float4*)B)[idx4];
    }
    __syncthreads();

    // log0 scaling in-smem: warp wid owns rows wid*4..wid*4+3; matmul below
    // only reads own-warp A rows, so no further barrier needed.
#pragma unroll
    for (int r = 0; r < 4; r++) {
        int row = wid * 4 + r;
        float4 v = ((float4*)As[row])[lane];
        float ss = wsum(v.x * v.x + v.y * v.y + v.z * v.z + v.w * v.w);
        float n = fmaxf(sqrtf(ss), HEPS);
        float s = atanhf(fminf(n, MAXT)) / n;
        ((float4*)As[row])[lane] = make_float4(v.x * s, v.y * s, v.z * s, v.w * s);
    }

    float acc[4][4];
#pragma unroll
    for (int r = 0; r < 4; r++)
#pragma unroll
        for (int c = 0; c < 4; c++) acc[r][c] = 0.f;

#pragma unroll 8
    for (int k4 = 0; k4 < 32; k4++) {
        float4 b0 = ((float4*)Bs[k4 * 4 + 0])[lane];
        float4 b1 = ((float4*)Bs[k4 * 4 + 1])[lane];
        float4 b2 = ((float4*)Bs[k4 * 4 + 2])[lane];
        float4 b3 = ((float4*)Bs[k4 * 4 + 3])[lane];
#pragma unroll
        for (int r = 0; r < 4; r++) {
            float4 a = ((float4*)As[wid * 4 + r])[k4];
            acc[r][0] += a.x * b0.x + a.y * b1.x + a.z * b2.x + a.w * b3.x;
            acc[r][1] += a.x * b0.y + a.y * b1.y + a.z * b2.y + a.w * b3.y;
            acc[r][2] += a.x * b0.z + a.y * b1.z + a.z * b2.z + a.w * b3.z;
            acc[r][3] += a.x * b0.w + a.y * b1.w + a.z * b2.w + a.w * b3.w;
        }
    }
    mobius_epi4<0>(acc, bias, br, wid, lane, out);
}

// ---------------------------------------------------------------------------
// GEMM2: out = h_add(exp0(W @ layer), lb), KD=256. Full A tile (32KB) + B in
// two 128x128 K-chunks (64KB). 8 warps x 4 rows.
// ---------------------------------------------------------------------------
__global__ __launch_bounds__(256) void k_gemm2(
    const float* __restrict__ A, const float* __restrict__ B,
    const float* __restrict__ bias, float* __restrict__ out) {
    extern __shared__ float sm[];
    float (*As)[2 * FD] = (float(*)[2 * FD])sm;         // 32 x 256
    float (*Bs)[FD] = (float(*)[FD])(sm + 32 * 2 * FD); // 128 x 128
    const int tid = threadIdx.x;
    const int lane = tid & 31;
    const int wid = tid >> 5;
    const int br = blockIdx.x * 32;

    // load full A tile: 2048 float4 / 256 = 8 iters
#pragma unroll
    for (int i = 0; i < 8; i++) {
        int idx4 = tid + i * 256;
        int r = idx4 >> 6, c4 = idx4 & 63;
        ((float4*)As[r])[c4] = ((const float4*)(A + (size_t)(br + r) * (2 * FD)))[c4];
    }

    float acc[4][4];
#pragma unroll
    for (int r = 0; r < 4; r++)
#pragma unroll
        for (int c = 0; c < 4; c++) acc[r][c] = 0.f;

#pragma unroll
    for (int chunk = 0; chunk < 2; chunk++) {
        __syncthreads();
        // load B chunk: rows chunk*128 .. +127, 4096 float4 / 256 = 16 iters
#pragma unroll
        for (int i = 0; i < 16; i++) {
            int idx4 = tid + i * 256;
            int k = idx4 >> 5, c4 = idx4 & 31;
            ((float4*)Bs[k])[c4] =
                ((const float4*)(B + (size_t)(chunk * FD) * FD))[idx4];
        }
        __syncthreads();
#pragma unroll 8
        for (int k4 = 0; k4 < 32; k4++) {
            float4 b0 = ((float4*)Bs[k4 * 4 + 0])[lane];
            float4 b1 = ((float4*)Bs[k4 * 4 + 1])[lane];
            float4 b2 = ((float4*)Bs[k4 * 4 + 2])[lane];
            float4 b3 = ((float4*)Bs[k4 * 4 + 3])[lane];
#pragma unroll
            for (int r = 0; r < 4; r++) {
                float4 a = ((float4*)As[wid * 4 + r])[chunk * 32 + k4];
                acc[r][0] += a.x * b0.x + a.y * b1.x + a.z * b2.x + a.w * b3.x;
                acc[r][1] += a.x * b0.y + a.y * b1.y + a.z * b2.y + a.w * b3.y;
                acc[r][2] += a.x * b0.z + a.y * b1.z + a.z * b2.z + a.w * b3.z;
                acc[r][3] += a.x * b0.w + a.y * b1.w + a.z * b2.w + a.w * b3.w;
            }
        }
    }
    mobius_epi4<1>(acc, bias, br, wid, lane, out);
}

// ---------------------------------------------------------------------------
// SpMM + concat/log fusion (R3-proven): W = log0(concat(x, exp0(adj @ V)))
// One warp per output row, scalar-ballot inner loop, one-chunk prefetch.
// ---------------------------------------------------------------------------
__global__ __launch_bounds__(256) void k_spmm_fused(
    const float* __restrict__ adj, const float* __restrict__ V,
    const float* __restrict__ x, float* __restrict__ W) {
    int row = (blockIdx.x * blockDim.x + threadIdx.x) >> 5;
    int lane = threadIdx.x & 31;
    if (row >= NN) return;
    const float* arow = adj + (size_t)row * NN;
    float ax = 0.f, ay = 0.f, az = 0.f, aw = 0.f;

    float cur[4];
#pragma unroll
    for (int q = 0; q < 4; q++) cur[q] = arow[q * 32 + lane];

    for (int base = 0; base < NN; base += 128) {
        float nxt[4] = {0.f, 0.f, 0.f, 0.f};
        int nb = base + 128;
        if (nb < NN) {
#pragma unroll
            for (int q = 0; q < 4; q++) nxt[q] = arow[nb + q * 32 + lane];
        }
#pragma unroll
        for (int q = 0; q < 4; q++) {
            unsigned m = __ballot_sync(0xffffffffu, cur[q] != 0.f);
            while (m) {
                int src = __ffs(m) - 1;
                m &= m - 1;
                float aj = __shfl_sync(0xffffffffu, cur[q], src);
                float4 v = ((const float4*)(V + (size_t)(base + q * 32 + src) * FD))[lane];
                ax += aj * v.x; ay += aj * v.y; az += aj * v.z; aw += aj * v.w;
            }
        }
#pragma unroll
        for (int q = 0; q < 4; q++) cur[q] = nxt[q];
    }

    // fused epilogue: W = log0(concat(x, exp0(AV)))
    float ssa = wsum(ax * ax + ay * ay + az * az + aw * aw);
    float na = fmaxf(sqrtf(ssa), HEPS);
    float sa = tanhf(na) / na;                 // neigh = sa * AV
    float4 xv = ((const float4*)(x + (size_t)row * FD))[lane];
    float ssx = wsum(xv.x * xv.x + xv.y * xv.y + xv.z * xv.z + xv.w * xv.w);
    float tot = ssx + sa * sa * ssa;           // ||concat||^2
    float n = fmaxf(sqrtf(tot), HEPS);
    float s = atanhf(fminf(n, MAXT)) / n;
    float* wr = W + (size_t)row * 2 * FD;
    ((float4*)wr)[lane] = make_float4(s * xv.x, s * xv.y, s * xv.z, s * xv.w);
    float sb = s * sa;
    ((float4*)(wr + FD))[lane] = make_float4(sb * ax, sb * ay, sb * az, sb * aw);
}

// ---------------------------------------------------------------------------
extern "C" void kernel_launch(void* const* d_in, const int* in_sizes, int n_in,
                              void* d_out, int out_size) {
    const float* x     = (const float*)d_in[0];
    const float* adj   = (const float*)d_in[1];
    const float* embed = (const float*)d_in[2];
    const float* layer = (const float*)d_in[3];
    const float* eb    = (const float*)d_in[4];
    const float* lb    = (const float*)d_in[5];
    float* out = (float*)d_out;
    (void)in_sizes; (void)n_in; (void)out_size;

    float *pV, *pW;
    cudaGetSymbolAddress((void**)&pV, g_V);
    cudaGetSymbolAddress((void**)&pW, g_W);

    const int smem1 = (32 * FD + FD * FD) * sizeof(float);        // 80 KB
    const int smem2 = (32 * 2 * FD + FD * FD) * sizeof(float);    // 96 KB
    cudaFuncSetAttribute(k_gemm1, cudaFuncAttributeMaxDynamicSharedMemorySize, smem1);
    cudaFuncSetAttribute(k_gemm2, cudaFuncAttributeMaxDynamicSharedMemorySize, smem2);

    // 1. V = log0(h_add(exp0(log0(x) @ embed), eb))
    k_gemm1<<<NN / 32, 256, smem1>>>(x, embed, eb, pV);
    // 2. W = log0(concat(x, exp0(adj @ V)))
    k_spmm_fused<<<NN / 8, 256>>>(adj, pV, x, pW);
    // 3. out = h_add(exp0(W @ layer), lb)
    k_gemm2<<<NN / 32, 256, smem2>>>(pW, layer, lb, out);
}

// round 7
// speedup vs baseline: 1.6333x; 1.1680x over previous
#include <cuda_runtime.h>
#include <math.h>
#include <stdint.h>

#define NN 8192
#define FD 128
#define HEPS 1e-7f
#define MAXT (1.0f - 1e-6f)
#define PA 132    // A/C smem row pad (fragment reads hit all 32 banks)
#define PB 136    // B smem row pad
#define PA2 260   // gemm2 A row pad (256+4)

// Scratch (no allocations allowed)
__device__ float g_V[NN * FD];
__device__ float g_W[NN * 2 * FD];

__device__ __forceinline__ float wsum(float v) {
#pragma unroll
    for (int o = 16; o > 0; o >>= 1) v += __shfl_xor_sync(0xffffffffu, v, o);
    return v;
}

__device__ __forceinline__ uint32_t f2tf(float f) {
    uint32_t u;
    asm("cvt.rna.tf32.f32 %0, %1;" : "=r"(u) : "f"(f));
    return u;
}

__device__ __forceinline__ void mma_tf32(float c[4], uint32_t a0, uint32_t a1,
                                         uint32_t a2, uint32_t a3,
                                         uint32_t b0, uint32_t b1) {
    asm volatile(
        "mma.sync.aligned.m16n8k8.row.col.f32.tf32.tf32.f32 "
        "{%0,%1,%2,%3},{%4,%5,%6,%7},{%8,%9},{%0,%1,%2,%3};"
        : "+f"(c[0]), "+f"(c[1]), "+f"(c[2]), "+f"(c[3])
        : "r"(a0), "r"(a1), "r"(a2), "r"(a3), "r"(b0), "r"(b1));
}

// Mobius epilogue reading staged accumulators from smem (warp owns 4 rows).
// MODE 0: log0(h_add(exp0(T),b)); MODE 1: h_add(exp0(T),b)
template <int MODE>
__device__ __forceinline__ void mobius_smem(const float* __restrict__ Cs,
                                            const float* __restrict__ bias,
                                            int br, int wid, int lane,
                                            float* __restrict__ out) {
    float4 bv = ((const float4*)bias)[lane];
    float y2 = wsum(bv.x * bv.x + bv.y * bv.y + bv.z * bv.z + bv.w * bv.w);
#pragma unroll
    for (int r = 0; r < 4; r++) {
        int lrow = wid * 4 + r;
        int row = br + lrow;
        float4 t = ((const float4*)(Cs + lrow * PA))[lane];
        float t0 = t.x, t1 = t.y, t2 = t.z, t3 = t.w;
        float ss  = wsum(t0 * t0 + t1 * t1 + t2 * t2 + t3 * t3);
        float dtb = wsum(t0 * bv.x + t1 * bv.y + t2 * bv.z + t3 * bv.w);
        float n = fmaxf(sqrtf(ss), HEPS);
        float s = tanhf(n) / n;                       // exp0 scale
        float x2 = s * s * ss;
        float xy = s * dtb;
        float cnum = 1.f + 2.f * xy + y2;
        float cx = 1.f - x2;
        float inv = 1.f / fmaxf(1.f + 2.f * xy + x2 * y2, HEPS);
        float o0 = (cnum * s * t0 + cx * bv.x) * inv;
        float o1 = (cnum * s * t1 + cx * bv.y) * inv;
        float o2 = (cnum * s * t2 + cx * bv.z) * inv;
        float o3 = (cnum * s * t3 + cx * bv.w) * inv;
        if (MODE == 0) {
            float sso = wsum(o0 * o0 + o1 * o1 + o2 * o2 + o3 * o3);
            float no = fmaxf(sqrtf(sso), HEPS);
            float so = atanhf(fminf(no, MAXT)) / no;
            o0 *= so; o1 *= so; o2 *= so; o3 *= so;
        }
        ((float4*)(out + (size_t)row * FD))[lane] = make_float4(o0, o1, o2, o3);
    }
}

// ---------------------------------------------------------------------------
// GEMM1 (tf32 mma): V = log0(h_add(exp0(log0(x) @ embed), eb))
// 256 thr, warps in 2x4 grid: each warp -> 16 rows x 32 cols of 32x128 tile.
// A scaled by log0 then cvt->tf32 in smem; B cvt at load. C staged via smem
// (reusing A region) into the warp-per-row Mobius epilogue.
// ---------------------------------------------------------------------------
__global__ __launch_bounds__(256) void k_gemm1(
    const float* __restrict__ X, const float* __restrict__ B,
    const float* __restrict__ bias, float* __restrict__ out) {
    extern __shared__ char smraw[];
    float*    Asf = (float*)smraw;                       // [32][PA]
    uint32_t* Asu = (uint32_t*)smraw;
    uint32_t* Bsu = (uint32_t*)(smraw + 32 * PA * 4);    // [128][PB]
    float*    Cs  = (float*)smraw;                       // [32][PA] (reuse)
    const int tid = threadIdx.x;
    const int lane = tid & 31;
    const int wid = tid >> 5;
    const int br = blockIdx.x * 32;

    // load A fp32
#pragma unroll
    for (int i = 0; i < 4; i++) {
        int idx4 = tid + i * 256;
        int r = idx4 >> 5, c4 = idx4 & 31;
        ((float4*)(Asf + r * PA))[c4] = ((const float4*)(X + (size_t)(br + r) * FD))[c4];
    }
    // load B, cvt -> tf32
#pragma unroll
    for (int i = 0; i < 16; i++) {
        int idx4 = tid + i * 256;
        int k = idx4 >> 5, c4 = idx4 & 31;
        float4 v = ((const float4*)B)[idx4];
        uint4 u = make_uint4(f2tf(v.x), f2tf(v.y), f2tf(v.z), f2tf(v.w));
        ((uint4*)(Bsu + k * PB))[c4] = u;
    }
    __syncthreads();

    // log0 scaling + cvt->tf32 in place: warp wid owns rows wid*4..+3
#pragma unroll
    for (int r = 0; r < 4; r++) {
        int row = wid * 4 + r;
        float4 v = ((float4*)(Asf + row * PA))[lane];
        float ss = wsum(v.x * v.x + v.y * v.y + v.z * v.z + v.w * v.w);
        float n = fmaxf(sqrtf(ss), HEPS);
        float s = atanhf(fminf(n, MAXT)) / n;
        uint4 u = make_uint4(f2tf(v.x * s), f2tf(v.y * s), f2tf(v.z * s), f2tf(v.w * s));
        ((uint4*)(Asu + row * PA))[lane] = u;
    }
    __syncthreads();

    // mma main loop
    const int qr = lane >> 2, qc = lane & 3;
    const int wm = (wid >> 2) * 16;       // 0 or 16
    const int wn = (wid & 3) * 32;        // 0,32,64,96
    float acc[4][4];
#pragma unroll
    for (int nt = 0; nt < 4; nt++)
#pragma unroll
        for (int c = 0; c < 4; c++) acc[nt][c] = 0.f;

#pragma unroll
    for (int ks = 0; ks < 16; ks++) {
        int k0 = ks * 8;
        uint32_t a0 = Asu[(wm + qr) * PA + k0 + qc];
        uint32_t a1 = Asu[(wm + 8 + qr) * PA + k0 + qc];
        uint32_t a2 = Asu[(wm + qr) * PA + k0 + 4 + qc];
        uint32_t a3 = Asu[(wm + 8 + qr) * PA + k0 + 4 + qc];
#pragma unroll
        for (int nt = 0; nt < 4; nt++) {
            int nb = wn + nt * 8;
            uint32_t b0 = Bsu[(k0 + qc) * PB + nb + qr];
            uint32_t b1 = Bsu[(k0 + 4 + qc) * PB + nb + qr];
            mma_tf32(acc[nt], a0, a1, a2, a3, b0, b1);
        }
    }
    __syncthreads();   // everyone done reading A before C overwrites it

    // stage C to smem
#pragma unroll
    for (int nt = 0; nt < 4; nt++) {
        int col = wn + nt * 8 + 2 * qc;
        *(float2*)&Cs[(wm + qr) * PA + col]     = make_float2(acc[nt][0], acc[nt][1]);
        *(float2*)&Cs[(wm + 8 + qr) * PA + col] = make_float2(acc[nt][2], acc[nt][3]);
    }
    __syncthreads();

    mobius_smem<0>(Cs, bias, br, wid, lane, out);
}

// ---------------------------------------------------------------------------
// GEMM2 (tf32 mma): out = h_add(exp0(W @ layer), lb), KD=256 in 2 B chunks.
// ---------------------------------------------------------------------------
__global__ __launch_bounds__(256) void k_gemm2(
    const float* __restrict__ A, const float* __restrict__ B,
    const float* __restrict__ bias, float* __restrict__ out) {
    extern __shared__ char smraw[];
    uint32_t* Asu = (uint32_t*)smraw;                     // [32][PA2]
    uint32_t* Bsu = (uint32_t*)(smraw + 32 * PA2 * 4);    // [128][PB]
    float*    Cs  = (float*)smraw;                        // [32][PA] (reuse A region)
    const int tid = threadIdx.x;
    const int lane = tid & 31;
    const int wid = tid >> 5;
    const int br = blockIdx.x * 32;

    // load A (32 x 256), cvt -> tf32
#pragma unroll
    for (int i = 0; i < 8; i++) {
        int idx4 = tid + i * 256;
        int r = idx4 >> 6, c4 = idx4 & 63;
        float4 v = ((const float4*)(A + (size_t)(br + r) * (2 * FD)))[c4];
        uint4 u = make_uint4(f2tf(v.x), f2tf(v.y), f2tf(v.z), f2tf(v.w));
        ((uint4*)(Asu + r * PA2))[c4] = u;
    }

    const int qr = lane >> 2, qc = lane & 3;
    const int wm = (wid >> 2) * 16;
    const int wn = (wid & 3) * 32;
    float acc[4][4];
#pragma unroll
    for (int nt = 0; nt < 4; nt++)
#pragma unroll
        for (int c = 0; c < 4; c++) acc[nt][c] = 0.f;

#pragma unroll
    for (int chunk = 0; chunk < 2; chunk++) {
        __syncthreads();
        // load B chunk rows chunk*128..+127, cvt
#pragma unroll
        for (int i = 0; i < 16; i++) {
            int idx4 = tid + i * 256;
            int k = idx4 >> 5, c4 = idx4 & 31;
            float4 v = ((const float4*)(B + (size_t)chunk * FD * FD))[idx4];
            uint4 u = make_uint4(f2tf(v.x), f2tf(v.y), f2tf(v.z), f2tf(v.w));
            ((uint4*)(Bsu + k * PB))[c4] = u;
        }
        __syncthreads();
#pragma unroll
        for (int ks = 0; ks < 16; ks++) {
            int k0 = ks * 8;                 // within-chunk B row
            int ka = chunk * FD + k0;        // A column
            uint32_t a0 = Asu[(wm + qr) * PA2 + ka + qc];
            uint32_t a1 = Asu[(wm + 8 + qr) * PA2 + ka + qc];
            uint32_t a2 = Asu[(wm + qr) * PA2 + ka + 4 + qc];
            uint32_t a3 = Asu[(wm + 8 + qr) * PA2 + ka + 4 + qc];
#pragma unroll
            for (int nt = 0; nt < 4; nt++) {
                int nb = wn + nt * 8;
                uint32_t b0 = Bsu[(k0 + qc) * PB + nb + qr];
                uint32_t b1 = Bsu[(k0 + 4 + qc) * PB + nb + qr];
                mma_tf32(acc[nt], a0, a1, a2, a3, b0, b1);
            }
        }
    }
    __syncthreads();

#pragma unroll
    for (int nt = 0; nt < 4; nt++) {
        int col = wn + nt * 8 + 2 * qc;
        *(float2*)&Cs[(wm + qr) * PA + col]     = make_float2(acc[nt][0], acc[nt][1]);
        *(float2*)&Cs[(wm + 8 + qr) * PA + col] = make_float2(acc[nt][2], acc[nt][3]);
    }
    __syncthreads();

    mobius_smem<1>(Cs, bias, br, wid, lane, out);
}

// ---------------------------------------------------------------------------
// SpMM + concat/log fusion (proven): W = log0(concat(x, exp0(adj @ V)))
// ---------------------------------------------------------------------------
__global__ __launch_bounds__(256) void k_spmm_fused(
    const float* __restrict__ adj, const float* __restrict__ V,
    const float* __restrict__ x, float* __restrict__ W) {
    int row = (blockIdx.x * blockDim.x + threadIdx.x) >> 5;
    int lane = threadIdx.x & 31;
    if (row >= NN) return;
    const float* arow = adj + (size_t)row * NN;
    float ax = 0.f, ay = 0.f, az = 0.f, aw = 0.f;

    float cur[4];
#pragma unroll
    for (int q = 0; q < 4; q++) cur[q] = arow[q * 32 + lane];

    for (int base = 0; base < NN; base += 128) {
        float nxt[4] = {0.f, 0.f, 0.f, 0.f};
        int nb = base + 128;
        if (nb < NN) {
#pragma unroll
            for (int q = 0; q < 4; q++) nxt[q] = arow[nb + q * 32 + lane];
        }
#pragma unroll
        for (int q = 0; q < 4; q++) {
            unsigned m = __ballot_sync(0xffffffffu, cur[q] != 0.f);
            while (m) {
                int src = __ffs(m) - 1;
                m &= m - 1;
                float aj = __shfl_sync(0xffffffffu, cur[q], src);
                float4 v = ((const float4*)(V + (size_t)(base + q * 32 + src) * FD))[lane];
                ax += aj * v.x; ay += aj * v.y; az += aj * v.z; aw += aj * v.w;
            }
        }
#pragma unroll
        for (int q = 0; q < 4; q++) cur[q] = nxt[q];
    }

    float ssa = wsum(ax * ax + ay * ay + az * az + aw * aw);
    float na = fmaxf(sqrtf(ssa), HEPS);
    float sa = tanhf(na) / na;
    float4 xv = ((const float4*)(x + (size_t)row * FD))[lane];
    float ssx = wsum(xv.x * xv.x + xv.y * xv.y + xv.z * xv.z + xv.w * xv.w);
    float tot = ssx + sa * sa * ssa;
    float n = fmaxf(sqrtf(tot), HEPS);
    float s = atanhf(fminf(n, MAXT)) / n;
    float* wr = W + (size_t)row * 2 * FD;
    ((float4*)wr)[lane] = make_float4(s * xv.x, s * xv.y, s * xv.z, s * xv.w);
    float sb = s * sa;
    ((float4*)(wr + FD))[lane] = make_float4(sb * ax, sb * ay, sb * az, sb * aw);
}

// ---------------------------------------------------------------------------
extern "C" void kernel_launch(void* const* d_in, const int* in_sizes, int n_in,
                              void* d_out, int out_size) {
    const float* x     = (const float*)d_in[0];
    const float* adj   = (const float*)d_in[1];
    const float* embed = (const float*)d_in[2];
    const float* layer = (const float*)d_in[3];
    const float* eb    = (const float*)d_in[4];
    const float* lb    = (const float*)d_in[5];
    float* out = (float*)d_out;
    (void)in_sizes; (void)n_in; (void)out_size;

    float *pV, *pW;
    cudaGetSymbolAddress((void**)&pV, g_V);
    cudaGetSymbolAddress((void**)&pW, g_W);

    const int smem1 = (32 * PA + 128 * PB) * 4;   // 86.5 KB
    const int smem2 = (32 * PA2 + 128 * PB) * 4;  // 102.9 KB
    cudaFuncSetAttribute(k_gemm1, cudaFuncAttributeMaxDynamicSharedMemorySize, smem1);
    cudaFuncSetAttribute(k_gemm2, cudaFuncAttributeMaxDynamicSharedMemorySize, smem2);

    // 1. V = log0(h_add(exp0(log0(x) @ embed), eb))
    k_gemm1<<<NN / 32, 256, smem1>>>(x, embed, eb, pV);
    // 2. W = log0(concat(x, exp0(adj @ V)))
    k_spmm_fused<<<NN / 8, 256>>>(adj, pV, x, pW);
    // 3. out = h_add(exp0(W @ layer), lb)
    k_gemm2<<<NN / 32, 256, smem2>>>(pW, layer, lb, out);
}